// round 4
// baseline (speedup 1.0000x reference)
#include <cuda_runtime.h>
#include <cstdint>

// Problem dims
#define BDIM 64
#define SDIM 512
#define IDIM 512
#define HDIM 1024
#define ODIM 512

static constexpr size_t SBH = (size_t)SDIM * BDIM * HDIM;   // 33,554,432

typedef unsigned long long ull;

// ---------------- f32x2 packed-FMA helpers (sm_103a FFMA2) ----------------
__device__ __forceinline__ ull pk2(float lo, float hi) {
    ull r; asm("mov.b64 %0, {%1, %2};" : "=l"(r) : "f"(lo), "f"(hi)); return r;
}
__device__ __forceinline__ void ffma2(ull& d, ull a, ull b) {
    asm("fma.rn.f32x2 %0, %1, %2, %0;" : "+l"(d) : "l"(a), "l"(b));
}
__device__ __forceinline__ float2 upk(ull v) {
    float2 f; asm("mov.b64 {%0, %1}, %2;" : "=f"(f.x), "=f"(f.y) : "l"(v)); return f;
}

// ---------------- device scratch (no allocations allowed) ----------------
__device__ float g_P0[SBH];   // x-proj gate z, layout [s][b][h] -- reused per layer
__device__ float g_P1[SBH];   // gate r
__device__ float g_P2[SBH];   // gate g
__device__ float g_Y[SBH];    // layer output [s][b][h] -- reused (Y0 then Y1)
__device__ float g_h[BDIM * HDIM];    // current hidden state
__device__ float g_rh[BDIM * HDIM];   // r * h
__device__ unsigned g_bar_count = 0;
__device__ unsigned g_bar_gen = 0;

// ---------------- persistent-scan config ----------------
#define NCTA 128            // 1 CTA/SM, single wave (<=148 SMs)
#define NJ 8                // hidden columns owned per CTA (128*8 = 1024)
#define CHUNK 256           // k-chunk staged in smem
#define HPAD 260            // hsb row stride ([b][k] layout, 16B-aligned, 2-way max conflict)
// smem layout (floats)
#define SM_WSZ 0
#define SM_WSR 8192
#define SM_WSG 16384
#define SM_HSB 24576
#define SM_ZS  (SM_HSB + BDIM * HPAD)       // 24576 + 16640 = 41216
#define SM_FLOATS (SM_ZS + 512)             // 41728
#define SMEM_BYTES (SM_FLOATS * 4)          // 166,912 B

// Grid-wide sense barrier. All NCTA CTAs co-resident (1 CTA/SM, grid=128<=148).
// Generation counter is monotonic across launches; each CTA snapshots the base at
// kernel start (stable: gen can't advance until every CTA arrives at barrier #1).
__device__ __forceinline__ void grid_barrier(unsigned* s_bar) {
    __threadfence();
    __syncthreads();
    if (threadIdx.x == 0) {
        unsigned target = ++(*s_bar);
        unsigned a = atomicAdd(&g_bar_count, 1u);
        if (a == NCTA - 1) {
            atomicExch(&g_bar_count, 0u);
            __threadfence();
            atomicExch(&g_bar_gen, target);
        } else {
            while ((int)(*(volatile unsigned*)&g_bar_gen - target) < 0) {
                __nanosleep(64);
            }
        }
        __threadfence();
    }
    __syncthreads();
}

// ---------------- SGEMM (FFMA2): C[row'(m)][n] = sum_k A[m][k]*B[k][n] + bias[n] ---------
// remap 0: row' = m                      (A rows already [s][b])
// remap 1: m = b*S+s  -> row' = s*64+b   (input -> projection layout)
// remap 2: m = s*B+b  -> row' = b*512+s  (Y1 -> final output (B,S,O))
__global__ __launch_bounds__(256)
void sgemm_kernel(const float* __restrict__ A, const float* __restrict__ Bm,
                  const float* __restrict__ bias, float* __restrict__ C,
                  int M, int N, int K, int remap)
{
    __shared__ float As2[16][256];   // A values DUPLICATED: row r at [kk][2r],[2r+1]
    __shared__ float Bs[16][128];
    const int tid = threadIdx.x;
    const int brow = blockIdx.y * 128;
    const int bcol = blockIdx.x * 128;
    const int tx = tid & 15;
    const int ty = tid >> 4;

    ull accp[8][4];                  // [row i][col-pair j]
#pragma unroll
    for (int i = 0; i < 8; i++)
#pragma unroll
        for (int j = 0; j < 4; j++) accp[i][j] = 0ull;

    for (int k0 = 0; k0 < K; k0 += 16) {
#pragma unroll
        for (int i = 0; i < 2; i++) {
            int f = i * 256 + tid;
            int ar = f >> 2, ak = (f & 3) * 4;
            float4 av = *(const float4*)&A[(size_t)(brow + ar) * K + k0 + ak];
            *(ull*)&As2[ak + 0][2 * ar] = pk2(av.x, av.x);
            *(ull*)&As2[ak + 1][2 * ar] = pk2(av.y, av.y);
            *(ull*)&As2[ak + 2][2 * ar] = pk2(av.z, av.z);
            *(ull*)&As2[ak + 3][2 * ar] = pk2(av.w, av.w);
            int bk = f >> 5, bc = (f & 31) * 4;
            *(float4*)&Bs[bk][bc] = *(const float4*)&Bm[(size_t)(k0 + bk) * N + bcol + bc];
        }
        __syncthreads();
#pragma unroll
        for (int kk = 0; kk < 16; kk++) {
            const ulonglong2* ap = (const ulonglong2*)&As2[kk][ty * 16];
            ulonglong2 a01 = ap[0], a23 = ap[1], a45 = ap[2], a67 = ap[3];
            const ulonglong2* bp = (const ulonglong2*)&Bs[kk][tx * 8];
            ulonglong2 b01 = bp[0], b23 = bp[1];
            ull ar8[8] = {a01.x, a01.y, a23.x, a23.y, a45.x, a45.y, a67.x, a67.y};
            ull br4[4] = {b01.x, b01.y, b23.x, b23.y};
#pragma unroll
            for (int i = 0; i < 8; i++)
#pragma unroll
                for (int j = 0; j < 4; j++) ffma2(accp[i][j], ar8[i], br4[j]);
        }
        __syncthreads();
    }

#pragma unroll
    for (int i = 0; i < 8; i++) {
        int m = brow + ty * 8 + i;
        int row;
        if (remap == 0) {
            row = m;
        } else if (remap == 1) {
            int b = m >> 9, s = m & 511;       // m = b*512+s
            row = s * 64 + b;
        } else {
            int s = m >> 6, b = m & 63;        // m = s*64+b
            row = b * 512 + s;
        }
        float* cp = &C[(size_t)row * N + bcol];
#pragma unroll
        for (int j4 = 0; j4 < 2; j4++) {
            int n = tx * 8 + j4 * 4;
            float4 bv = *(const float4*)&bias[bcol + n];
            float2 p0 = upk(accp[i][j4 * 2 + 0]);
            float2 p1 = upk(accp[i][j4 * 2 + 1]);
            float4 v;
            v.x = p0.x + bv.x;
            v.y = p0.y + bv.y;
            v.z = p1.x + bv.z;
            v.w = p1.y + bv.w;
            *(float4*)&cp[n] = v;
        }
    }
}

// ---------------- persistent GRU scan (FFMA2 inner loops) ----------------
// One CTA owns NJ=8 hidden columns. Recurrent weight slices live in smem for the
// whole 512-step scan. Two grid barriers per step:
//   phase1: z,r = sigmoid(P + h@W) ; publish r*h     (z kept in smem)
//   phase2: g = tanh(Pg + (r*h)@Wg) ; h = z*h+(1-z)*g ; publish h and Y[t]
__global__ __launch_bounds__(256, 1)
void scan_kernel(const float* __restrict__ Whz, const float* __restrict__ Whr,
                 const float* __restrict__ Whg,
                 const float* __restrict__ h0,    // hidden_state input (B, 2, H)
                 int layer,
                 float* __restrict__ hfin)        // d_out hidden section (B, 2, H)
{
    extern __shared__ float sm[];
    float* wsz = sm + SM_WSZ;
    float* wsr = sm + SM_WSR;
    float* wsg = sm + SM_WSG;
    float* hsb = sm + SM_HSB;    // [b][k] staged chunk, row stride HPAD
    float* zs  = sm + SM_ZS;     // z gate values for our 8 columns [b][8]
    __shared__ unsigned s_bar;

    const int tid = threadIdx.x;
    const int j0 = blockIdx.x * NJ;

    if (tid == 0) s_bar = *(volatile unsigned*)&g_bar_gen;

    // stage recurrent weight slices (constant across all 512 steps); layout [k][8]
    for (int idx = tid; idx < HDIM * NJ; idx += 256) {
        int k = idx >> 3, jj = idx & 7;
        wsz[idx] = Whz[(size_t)k * HDIM + j0 + jj];
        wsr[idx] = Whr[(size_t)k * HDIM + j0 + jj];
        wsg[idx] = Whg[(size_t)k * HDIM + j0 + jj];
    }
    // init hidden state (our columns)
    for (int idx = tid; idx < BDIM * NJ; idx += 256) {
        int b = idx >> 3, jj = idx & 7;
        g_h[b * HDIM + j0 + jj] = h0[b * (2 * HDIM) + layer * HDIM + j0 + jj];
    }
    grid_barrier(&s_bar);

    // phase-1 mapping: 256 threads = 2 gates x 64 batch x 2 float4-col-groups
    const int gate = tid >> 7;             // 0 = z, 1 = r
    const int b1 = (tid >> 1) & 63;
    const int q1 = tid & 1;
    const int col1 = j0 + q1 * 4;
    const float* wsA = gate ? wsr : wsz;
    const float* Pzr = gate ? g_P1 : g_P0;

    // phase-2 mapping (threads 0..127): 64 batch x 2 float4-col-groups
    const int b2 = tid >> 1;
    const int q2 = tid & 1;
    const int col2 = j0 + q2 * 4;

    for (int t = 0; t < SDIM; t++) {
        // ================= phase 1: z and r =================
        ull ac0 = 0ull, ac1 = 0ull;
        for (int c = 0; c < 4; c++) {
            const int kk = c * CHUNK;
            // stage h chunk: coalesced float4 global read -> [b][k] smem
#pragma unroll
            for (int it = 0; it < 16; it++) {
                int f = it * 256 + tid;            // one float4 each; 4096 total
                int bb = f >> 6, kc = (f & 63) * 4;
                *(float4*)&hsb[bb * HPAD + kc] =
                    *(const float4*)&g_h[bb * HDIM + kk + kc];
            }
            __syncthreads();
            const float* wp = wsA + kk * 8 + q1 * 4;
            const float* hrow = &hsb[b1 * HPAD];
#pragma unroll 4
            for (int k4 = 0; k4 < CHUNK; k4 += 4) {
                float4 h4 = *(const float4*)&hrow[k4];
                ulonglong2 w0 = *(const ulonglong2*)(wp + (k4 + 0) * 8);
                ulonglong2 w1 = *(const ulonglong2*)(wp + (k4 + 1) * 8);
                ulonglong2 w2 = *(const ulonglong2*)(wp + (k4 + 2) * 8);
                ulonglong2 w3 = *(const ulonglong2*)(wp + (k4 + 3) * 8);
                ull hp0 = pk2(h4.x, h4.x);
                ull hp1 = pk2(h4.y, h4.y);
                ull hp2 = pk2(h4.z, h4.z);
                ull hp3 = pk2(h4.w, h4.w);
                ffma2(ac0, hp0, w0.x); ffma2(ac1, hp0, w0.y);
                ffma2(ac0, hp1, w1.x); ffma2(ac1, hp1, w1.y);
                ffma2(ac0, hp2, w2.x); ffma2(ac1, hp2, w2.y);
                ffma2(ac0, hp3, w3.x); ffma2(ac1, hp3, w3.y);
            }
            __syncthreads();
        }
        {
            float2 axy = upk(ac0);
            float2 azw = upk(ac1);
            float4 p = *(const float4*)&Pzr[(size_t)t * BDIM * HDIM + b1 * HDIM + col1];
            float4 v;
            v.x = 1.f / (1.f + expf(-(axy.x + p.x)));
            v.y = 1.f / (1.f + expf(-(axy.y + p.y)));
            v.z = 1.f / (1.f + expf(-(azw.x + p.z)));
            v.w = 1.f / (1.f + expf(-(azw.y + p.w)));
            if (gate == 0) {
                *(float4*)&zs[b1 * 8 + q1 * 4] = v;
            } else {
                float4 ho = *(const float4*)&g_h[b1 * HDIM + col1];
                float4 rh = make_float4(v.x * ho.x, v.y * ho.y, v.z * ho.z, v.w * ho.w);
                *(float4*)&g_rh[b1 * HDIM + col1] = rh;
            }
        }
        grid_barrier(&s_bar);

        // ================= phase 2: g and h update =================
        ull bc0 = 0ull, bc1 = 0ull;
        for (int c = 0; c < 4; c++) {
            const int kk = c * CHUNK;
#pragma unroll
            for (int it = 0; it < 16; it++) {
                int f = it * 256 + tid;
                int bb = f >> 6, kc = (f & 63) * 4;
                *(float4*)&hsb[bb * HPAD + kc] =
                    *(const float4*)&g_rh[bb * HDIM + kk + kc];
            }
            __syncthreads();
            if (tid < 128) {
                const float* wp = wsg + kk * 8 + q2 * 4;
                const float* hrow = &hsb[b2 * HPAD];
#pragma unroll 4
                for (int k4 = 0; k4 < CHUNK; k4 += 4) {
                    float4 h4 = *(const float4*)&hrow[k4];
                    ulonglong2 w0 = *(const ulonglong2*)(wp + (k4 + 0) * 8);
                    ulonglong2 w1 = *(const ulonglong2*)(wp + (k4 + 1) * 8);
                    ulonglong2 w2 = *(const ulonglong2*)(wp + (k4 + 2) * 8);
                    ulonglong2 w3 = *(const ulonglong2*)(wp + (k4 + 3) * 8);
                    ull hp0 = pk2(h4.x, h4.x);
                    ull hp1 = pk2(h4.y, h4.y);
                    ull hp2 = pk2(h4.z, h4.z);
                    ull hp3 = pk2(h4.w, h4.w);
                    ffma2(bc0, hp0, w0.x); ffma2(bc1, hp0, w0.y);
                    ffma2(bc0, hp1, w1.x); ffma2(bc1, hp1, w1.y);
                    ffma2(bc0, hp2, w2.x); ffma2(bc1, hp2, w2.y);
                    ffma2(bc0, hp3, w3.x); ffma2(bc1, hp3, w3.y);
                }
            }
            __syncthreads();
        }
        if (tid < 128) {
            float2 axy = upk(bc0);
            float2 azw = upk(bc1);
            float4 p = *(const float4*)&g_P2[(size_t)t * BDIM * HDIM + b2 * HDIM + col2];
            float4 g4;
            g4.x = tanhf(axy.x + p.x);
            g4.y = tanhf(axy.y + p.y);
            g4.z = tanhf(azw.x + p.z);
            g4.w = tanhf(azw.y + p.w);
            float4 z4 = *(const float4*)&zs[b2 * 8 + q2 * 4];
            float4 ho = *(const float4*)&g_h[b2 * HDIM + col2];
            float4 hn;
            hn.x = z4.x * ho.x + (1.f - z4.x) * g4.x;
            hn.y = z4.y * ho.y + (1.f - z4.y) * g4.y;
            hn.z = z4.z * ho.z + (1.f - z4.z) * g4.z;
            hn.w = z4.w * ho.w + (1.f - z4.w) * g4.w;
            *(float4*)&g_h[b2 * HDIM + col2] = hn;
            *(float4*)&g_Y[(size_t)t * BDIM * HDIM + b2 * HDIM + col2] = hn;
        }
        grid_barrier(&s_bar);
    }

    // write final hidden state for this layer
    for (int idx = tid; idx < BDIM * NJ; idx += 256) {
        int b = idx >> 3, jj = idx & 7;
        hfin[b * (2 * HDIM) + layer * HDIM + j0 + jj] = g_h[b * HDIM + j0 + jj];
    }
}

// ---------------- launch ----------------
extern "C" void kernel_launch(void* const* d_in, const int* in_sizes, int n_in,
                              void* d_out, int out_size)
{
    const float* input  = (const float*)d_in[0];
    const float* hidden = (const float*)d_in[1];
    const float* wxz0 = (const float*)d_in[2];
    const float* whz0 = (const float*)d_in[3];
    const float* bhz0 = (const float*)d_in[4];
    const float* wxr0 = (const float*)d_in[5];
    const float* whr0 = (const float*)d_in[6];
    const float* bhr0 = (const float*)d_in[7];
    const float* wxg0 = (const float*)d_in[8];
    const float* whg0 = (const float*)d_in[9];
    const float* bhg0 = (const float*)d_in[10];
    const float* wxz1 = (const float*)d_in[11];
    const float* whz1 = (const float*)d_in[12];
    const float* bhz1 = (const float*)d_in[13];
    const float* wxr1 = (const float*)d_in[14];
    const float* whr1 = (const float*)d_in[15];
    const float* bhr1 = (const float*)d_in[16];
    const float* wxg1 = (const float*)d_in[17];
    const float* whg1 = (const float*)d_in[18];
    const float* bhg1 = (const float*)d_in[19];
    const float* why_w = (const float*)d_in[20];
    const float* why_b = (const float*)d_in[21];

    float* out = (float*)d_out;
    float* hfin = out + (size_t)BDIM * SDIM * ODIM;

    static float* pP0 = []() { void* p; cudaGetSymbolAddress(&p, g_P0); return (float*)p; }();
    static float* pP1 = []() { void* p; cudaGetSymbolAddress(&p, g_P1); return (float*)p; }();
    static float* pP2 = []() { void* p; cudaGetSymbolAddress(&p, g_P2); return (float*)p; }();
    static float* pY  = []() { void* p; cudaGetSymbolAddress(&p, g_Y);  return (float*)p; }();
    static int smem_ok = []() {
        return (int)cudaFuncSetAttribute(scan_kernel,
                                         cudaFuncAttributeMaxDynamicSharedMemorySize,
                                         SMEM_BYTES);
    }();
    (void)smem_ok;

    const int M = BDIM * SDIM;              // 32768
    dim3 gH(HDIM / 128, M / 128);           // (8, 256)
    dim3 gO(ODIM / 128, M / 128);           // (4, 256)

    // layer 0 x-projections: A = input (rows m=b*S+s, K=I), out [s][b][h]
    sgemm_kernel<<<gH, 256>>>(input, wxz0, bhz0, pP0, M, HDIM, IDIM, 1);
    sgemm_kernel<<<gH, 256>>>(input, wxr0, bhr0, pP1, M, HDIM, IDIM, 1);
    sgemm_kernel<<<gH, 256>>>(input, wxg0, bhg0, pP2, M, HDIM, IDIM, 1);

    // layer 0 scan -> g_Y
    scan_kernel<<<NCTA, 256, SMEM_BYTES>>>(whz0, whr0, whg0, hidden, 0, hfin);

    // layer 1 x-projections: A = g_Y (rows m=s*B+b, K=H), out same layout
    sgemm_kernel<<<gH, 256>>>(pY, wxz1, bhz1, pP0, M, HDIM, HDIM, 0);
    sgemm_kernel<<<gH, 256>>>(pY, wxr1, bhr1, pP1, M, HDIM, HDIM, 0);
    sgemm_kernel<<<gH, 256>>>(pY, wxg1, bhg1, pP2, M, HDIM, HDIM, 0);

    // layer 1 scan -> g_Y (overwrites Y0, no longer needed)
    scan_kernel<<<NCTA, 256, SMEM_BYTES>>>(whz1, whr1, whg1, hidden, 1, hfin);

    // output projection: (B,S,O)
    sgemm_kernel<<<gO, 256>>>(pY, why_w, why_b, out, M, ODIM, HDIM, 2);
}

// round 6
// speedup vs baseline: 1.0910x; 1.0910x over previous
#include <cuda_runtime.h>
#include <cstdint>

// Problem dims
#define BDIM 64
#define SDIM 512
#define IDIM 512
#define HDIM 1024
#define ODIM 512

static constexpr size_t SBH = (size_t)SDIM * BDIM * HDIM;   // 33,554,432

typedef unsigned long long ull;

// ---------------- f32x2 packed-FMA helpers (sm_103a FFMA2) ----------------
__device__ __forceinline__ ull pk2(float lo, float hi) {
    ull r; asm("mov.b64 %0, {%1, %2};" : "=l"(r) : "f"(lo), "f"(hi)); return r;
}
__device__ __forceinline__ void ffma2(ull& d, ull a, ull b) {
    asm("fma.rn.f32x2 %0, %1, %2, %0;" : "+l"(d) : "l"(a), "l"(b));
}
__device__ __forceinline__ float2 upk(ull v) {
    float2 f; asm("mov.b64 {%0, %1}, %2;" : "=f"(f.x), "=f"(f.y) : "l"(v)); return f;
}

// ---------------- cp.async helpers ----------------
__device__ __forceinline__ void cpasync16(void* smem_dst, const void* gsrc) {
    unsigned s = (unsigned)__cvta_generic_to_shared(smem_dst);
    asm volatile("cp.async.cg.shared.global [%0], [%1], 16;" :: "r"(s), "l"(gsrc));
}
#define CP_COMMIT() asm volatile("cp.async.commit_group;" ::: "memory")
#define CP_WAIT(n)  asm volatile("cp.async.wait_group %0;" :: "n"(n) : "memory")

// ---------------- device scratch (no allocations allowed) ----------------
__device__ float g_P0[SBH];   // x-proj gate z, layout [s][b][h] -- reused per layer
__device__ float g_P1[SBH];   // gate r
__device__ float g_P2[SBH];   // gate g
__device__ float g_Y[SBH];    // layer output [s][b][h] -- reused (Y0 then Y1)
__device__ float g_h[BDIM * HDIM];    // current hidden state
__device__ float g_rh[BDIM * HDIM];   // r * h
__device__ unsigned g_bar_count[32];  // separate 128B lines for count vs gen
__device__ unsigned g_bar_gen[32];

// ---------------- persistent-scan config ----------------
#define NCTA 128            // 1 CTA/SM, single wave
#define NJ 8                // hidden columns owned per CTA (128*8 = 1024)
#define CHUNK 128           // k-chunk staged in smem
#define NCHUNK 8            // 1024 / 128
#define HPAD 132            // [b][k] row stride (16B aligned, 2-way max bank conflict)
#define BUFSZ (BDIM * HPAD) // 8448 floats per buffer
// smem layout (floats): wsz[8192] wsr[8192] wsg[8192] hsb[3][BUFSZ]
#define SM_WSZ 0
#define SM_WSR 8192
#define SM_WSG 16384
#define SM_HSB 24576
#define SM_FLOATS (SM_HSB + 3 * BUFSZ)      // 49920
#define SMEM_BYTES (SM_FLOATS * 4)          // 199,680 B

// Grid-wide sense barrier. All NCTA CTAs co-resident (1 CTA/SM, grid=128).
// Generation counter monotonic across launches; each CTA snapshots at start.
__device__ __forceinline__ void grid_barrier(unsigned* s_bar) {
    __threadfence();
    __syncthreads();
    if (threadIdx.x == 0) {
        unsigned target = ++(*s_bar);
        unsigned a = atomicAdd(&g_bar_count[0], 1u);
        if (a == NCTA - 1) {
            g_bar_count[0] = 0;
            __threadfence();
            atomicExch(&g_bar_gen[0], target);
        } else {
            while ((int)(*(volatile unsigned*)&g_bar_gen[0] - target) < 0) {
                __nanosleep(16);
            }
        }
        __threadfence();
    }
    __syncthreads();
}

// ---------------- SGEMM (FFMA2): C[row'(m)][n] = sum_k A[m][k]*B[k][n] + bias[n] ---------
// remap 0: row' = m                      (A rows already [s][b])
// remap 1: m = b*S+s  -> row' = s*64+b   (input -> projection layout)
// remap 2: m = s*B+b  -> row' = b*512+s  (Y1 -> final output (B,S,O))
__global__ __launch_bounds__(256)
void sgemm_kernel(const float* __restrict__ A, const float* __restrict__ Bm,
                  const float* __restrict__ bias, float* __restrict__ C,
                  int M, int N, int K, int remap)
{
    __shared__ float As2[16][256];   // A values DUPLICATED: row r at [kk][2r],[2r+1]
    __shared__ float Bs[16][128];
    const int tid = threadIdx.x;
    const int brow = blockIdx.y * 128;
    const int bcol = blockIdx.x * 128;
    const int tx = tid & 15;
    const int ty = tid >> 4;

    ull accp[8][4];                  // [row i][col-pair j]
#pragma unroll
    for (int i = 0; i < 8; i++)
#pragma unroll
        for (int j = 0; j < 4; j++) accp[i][j] = 0ull;

    for (int k0 = 0; k0 < K; k0 += 16) {
#pragma unroll
        for (int i = 0; i < 2; i++) {
            int f = i * 256 + tid;
            int ar = f >> 2, ak = (f & 3) * 4;
            float4 av = *(const float4*)&A[(size_t)(brow + ar) * K + k0 + ak];
            *(ull*)&As2[ak + 0][2 * ar] = pk2(av.x, av.x);
            *(ull*)&As2[ak + 1][2 * ar] = pk2(av.y, av.y);
            *(ull*)&As2[ak + 2][2 * ar] = pk2(av.z, av.z);
            *(ull*)&As2[ak + 3][2 * ar] = pk2(av.w, av.w);
            int bk = f >> 5, bc = (f & 31) * 4;
            *(float4*)&Bs[bk][bc] = *(const float4*)&Bm[(size_t)(k0 + bk) * N + bcol + bc];
        }
        __syncthreads();
#pragma unroll
        for (int kk = 0; kk < 16; kk++) {
            const ulonglong2* ap = (const ulonglong2*)&As2[kk][ty * 16];
            ulonglong2 a01 = ap[0], a23 = ap[1], a45 = ap[2], a67 = ap[3];
            const ulonglong2* bp = (const ulonglong2*)&Bs[kk][tx * 8];
            ulonglong2 b01 = bp[0], b23 = bp[1];
            ull ar8[8] = {a01.x, a01.y, a23.x, a23.y, a45.x, a45.y, a67.x, a67.y};
            ull br4[4] = {b01.x, b01.y, b23.x, b23.y};
#pragma unroll
            for (int i = 0; i < 8; i++)
#pragma unroll
                for (int j = 0; j < 4; j++) ffma2(accp[i][j], ar8[i], br4[j]);
        }
        __syncthreads();
    }

#pragma unroll
    for (int i = 0; i < 8; i++) {
        int m = brow + ty * 8 + i;
        int row;
        if (remap == 0) {
            row = m;
        } else if (remap == 1) {
            int b = m >> 9, s = m & 511;       // m = b*512+s
            row = s * 64 + b;
        } else {
            int s = m >> 6, b = m & 63;        // m = s*64+b
            row = b * 512 + s;
        }
        float* cp = &C[(size_t)row * N + bcol];
#pragma unroll
        for (int j4 = 0; j4 < 2; j4++) {
            int n = tx * 8 + j4 * 4;
            float4 bv = *(const float4*)&bias[bcol + n];
            float2 p0 = upk(accp[i][j4 * 2 + 0]);
            float2 p1 = upk(accp[i][j4 * 2 + 1]);
            float4 v;
            v.x = p0.x + bv.x;
            v.y = p0.y + bv.y;
            v.z = p1.x + bv.z;
            v.w = p1.y + bv.w;
            *(float4*)&cp[n] = v;
        }
    }
}

// ---------------- persistent GRU scan ----------------
// One CTA owns NJ=8 hidden columns; recurrent weight slices live in smem for the
// whole scan. Triple-buffered cp.async staging of h / r*h overlaps with compute.
// Two grid barriers per step.
__device__ __forceinline__ void stage_chunk(float* buf, const float* __restrict__ src,
                                            int kk, int tid) {
#pragma unroll
    for (int it = 0; it < 8; it++) {
        int f = it * 256 + tid;              // 2048 float4 per chunk
        int bb = f >> 5, kc = (f & 31) * 4;
        cpasync16(&buf[bb * HPAD + kc], &src[bb * HDIM + kk + kc]);
    }
    CP_COMMIT();
}

__device__ __forceinline__ void chunk_mac(ull& a0, ull& a1,
                                          const float* __restrict__ hrow,
                                          const float* __restrict__ wp) {
#pragma unroll 8
    for (int k4 = 0; k4 < CHUNK; k4 += 4) {
        float4 h4 = *(const float4*)&hrow[k4];
        ulonglong2 w0 = *(const ulonglong2*)(wp + (k4 + 0) * 8);
        ulonglong2 w1 = *(const ulonglong2*)(wp + (k4 + 1) * 8);
        ulonglong2 w2 = *(const ulonglong2*)(wp + (k4 + 2) * 8);
        ulonglong2 w3 = *(const ulonglong2*)(wp + (k4 + 3) * 8);
        ull hp0 = pk2(h4.x, h4.x);
        ull hp1 = pk2(h4.y, h4.y);
        ull hp2 = pk2(h4.z, h4.z);
        ull hp3 = pk2(h4.w, h4.w);
        ffma2(a0, hp0, w0.x); ffma2(a1, hp0, w0.y);
        ffma2(a0, hp1, w1.x); ffma2(a1, hp1, w1.y);
        ffma2(a0, hp2, w2.x); ffma2(a1, hp2, w2.y);
        ffma2(a0, hp3, w3.x); ffma2(a1, hp3, w3.y);
    }
}

__global__ __launch_bounds__(256, 1)
void scan_kernel(const float* __restrict__ Whz, const float* __restrict__ Whr,
                 const float* __restrict__ Whg,
                 const float* __restrict__ h0,    // hidden_state input (B, 2, H)
                 int layer,
                 float* __restrict__ hfin)        // d_out hidden section (B, 2, H)
{
    extern __shared__ float sm[];
    float* wsz = sm + SM_WSZ;
    float* wsr = sm + SM_WSR;
    float* wsg = sm + SM_WSG;
    float* bufs[3] = { sm + SM_HSB, sm + SM_HSB + BUFSZ, sm + SM_HSB + 2 * BUFSZ };
    __shared__ unsigned s_bar;

    const int tid = threadIdx.x;
    const int j0 = blockIdx.x * NJ;

    if (tid == 0) s_bar = *(volatile unsigned*)&g_bar_gen[0];

    // stage recurrent weight slices (constant across all steps); layout [k][8]
    for (int idx = tid; idx < HDIM * NJ; idx += 256) {
        int k = idx >> 3, jj = idx & 7;
        wsz[idx] = Whz[(size_t)k * HDIM + j0 + jj];
        wsr[idx] = Whr[(size_t)k * HDIM + j0 + jj];
        wsg[idx] = Whg[(size_t)k * HDIM + j0 + jj];
    }
    // init hidden state (our columns)
    for (int idx = tid; idx < BDIM * NJ; idx += 256) {
        int b = idx >> 3, jj = idx & 7;
        g_h[b * HDIM + j0 + jj] = h0[b * (2 * HDIM) + layer * HDIM + j0 + jj];
    }
    grid_barrier(&s_bar);

    // phase-1 mapping: 256 threads = 2 gates x 64 batch x 2 float4-col-groups
    const int gate = tid >> 7;             // 0 = z (tid<128), 1 = r
    const int b1 = (tid >> 1) & 63;
    const int q1 = tid & 1;
    const int col1 = j0 + q1 * 4;
    const float* wsA = gate ? wsr : wsz;
    const float* Pzr = gate ? g_P1 : g_P0;

    for (int t = 0; t < SDIM; t++) {
        const size_t poff = (size_t)t * BDIM * HDIM + (size_t)b1 * HDIM + col1;

        // ================= phase 1: z and r =================
        float4 pv = __ldg((const float4*)&Pzr[poff]);
        float4 ho = *(const float4*)&g_h[b1 * HDIM + col1];   // own-SM columns
        ull ac0 = 0ull, ac1 = 0ull;

        stage_chunk(bufs[0], g_h, 0, tid);
#pragma unroll
        for (int c = 0; c < NCHUNK; c++) {
            if (c + 1 < NCHUNK) {
                stage_chunk(bufs[(c + 1) % 3], g_h, (c + 1) * CHUNK, tid);
                CP_WAIT(1);
            } else {
                CP_WAIT(0);
            }
            __syncthreads();
            chunk_mac(ac0, ac1, &bufs[c % 3][b1 * HPAD], wsA + c * CHUNK * 8 + q1 * 4);
        }

        float2 axy = upk(ac0);
        float2 azw = upk(ac1);
        float4 v;
        v.x = 1.f / (1.f + expf(-(axy.x + pv.x)));
        v.y = 1.f / (1.f + expf(-(axy.y + pv.y)));
        v.z = 1.f / (1.f + expf(-(azw.x + pv.z)));
        v.w = 1.f / (1.f + expf(-(azw.y + pv.w)));
        float4 z4 = v;                       // meaningful for gate==0 (kept in regs)
        if (gate == 1) {
            float4 rh = make_float4(v.x * ho.x, v.y * ho.y, v.z * ho.z, v.w * ho.w);
            *(float4*)&g_rh[b1 * HDIM + col1] = rh;
        }
        grid_barrier(&s_bar);

        // ================= phase 2: g and h update =================
        float4 p2v;
        if (gate == 0) p2v = __ldg((const float4*)&g_P2[poff]);
        ull bc0 = 0ull, bc1 = 0ull;

        stage_chunk(bufs[0], g_rh, 0, tid);
#pragma unroll
        for (int c = 0; c < NCHUNK; c++) {
            if (c + 1 < NCHUNK) {
                stage_chunk(bufs[(c + 1) % 3], g_rh, (c + 1) * CHUNK, tid);
                CP_WAIT(1);
            } else {
                CP_WAIT(0);
            }
            __syncthreads();
            if (gate == 0)
                chunk_mac(bc0, bc1, &bufs[c % 3][b1 * HPAD], wsg + c * CHUNK * 8 + q1 * 4);
        }

        if (gate == 0) {
            float2 gxy = upk(bc0);
            float2 gzw = upk(bc1);
            float4 g4;
            g4.x = tanhf(gxy.x + p2v.x);
            g4.y = tanhf(gxy.y + p2v.y);
            g4.z = tanhf(gzw.x + p2v.z);
            g4.w = tanhf(gzw.y + p2v.w);
            float4 hn;
            hn.x = z4.x * ho.x + (1.f - z4.x) * g4.x;
            hn.y = z4.y * ho.y + (1.f - z4.y) * g4.y;
            hn.z = z4.z * ho.z + (1.f - z4.z) * g4.z;
            hn.w = z4.w * ho.w + (1.f - z4.w) * g4.w;
            *(float4*)&g_h[b1 * HDIM + col1] = hn;
            *(float4*)&g_Y[(size_t)t * BDIM * HDIM + b1 * HDIM + col1] = hn;
        }
        grid_barrier(&s_bar);
    }

    // write final hidden state for this layer
    for (int idx = tid; idx < BDIM * NJ; idx += 256) {
        int b = idx >> 3, jj = idx & 7;
        hfin[b * (2 * HDIM) + layer * HDIM + j0 + jj] = g_h[b * HDIM + j0 + jj];
    }
}

// ---------------- launch ----------------
extern "C" void kernel_launch(void* const* d_in, const int* in_sizes, int n_in,
                              void* d_out, int out_size)
{
    const float* input  = (const float*)d_in[0];
    const float* hidden = (const float*)d_in[1];
    const float* wxz0 = (const float*)d_in[2];
    const float* whz0 = (const float*)d_in[3];
    const float* bhz0 = (const float*)d_in[4];
    const float* wxr0 = (const float*)d_in[5];
    const float* whr0 = (const float*)d_in[6];
    const float* bhr0 = (const float*)d_in[7];
    const float* wxg0 = (const float*)d_in[8];
    const float* whg0 = (const float*)d_in[9];
    const float* bhg0 = (const float*)d_in[10];
    const float* wxz1 = (const float*)d_in[11];
    const float* whz1 = (const float*)d_in[12];
    const float* bhz1 = (const float*)d_in[13];
    const float* wxr1 = (const float*)d_in[14];
    const float* whr1 = (const float*)d_in[15];
    const float* bhr1 = (const float*)d_in[16];
    const float* wxg1 = (const float*)d_in[17];
    const float* whg1 = (const float*)d_in[18];
    const float* bhg1 = (const float*)d_in[19];
    const float* why_w = (const float*)d_in[20];
    const float* why_b = (const float*)d_in[21];

    float* out = (float*)d_out;
    float* hfin = out + (size_t)BDIM * SDIM * ODIM;

    static float* pP0 = []() { void* p; cudaGetSymbolAddress(&p, g_P0); return (float*)p; }();
    static float* pP1 = []() { void* p; cudaGetSymbolAddress(&p, g_P1); return (float*)p; }();
    static float* pP2 = []() { void* p; cudaGetSymbolAddress(&p, g_P2); return (float*)p; }();
    static float* pY  = []() { void* p; cudaGetSymbolAddress(&p, g_Y);  return (float*)p; }();
    static int smem_ok = []() {
        return (int)cudaFuncSetAttribute(scan_kernel,
                                         cudaFuncAttributeMaxDynamicSharedMemorySize,
                                         SMEM_BYTES);
    }();
    (void)smem_ok;

    const int M = BDIM * SDIM;              // 32768
    dim3 gH(HDIM / 128, M / 128);           // (8, 256)
    dim3 gO(ODIM / 128, M / 128);           // (4, 256)

    // layer 0 x-projections: A = input (rows m=b*S+s, K=I), out [s][b][h]
    sgemm_kernel<<<gH, 256>>>(input, wxz0, bhz0, pP0, M, HDIM, IDIM, 1);
    sgemm_kernel<<<gH, 256>>>(input, wxr0, bhr0, pP1, M, HDIM, IDIM, 1);
    sgemm_kernel<<<gH, 256>>>(input, wxg0, bhg0, pP2, M, HDIM, IDIM, 1);

    // layer 0 scan -> g_Y
    scan_kernel<<<NCTA, 256, SMEM_BYTES>>>(whz0, whr0, whg0, hidden, 0, hfin);

    // layer 1 x-projections: A = g_Y (rows m=s*B+b, K=H), out same layout
    sgemm_kernel<<<gH, 256>>>(pY, wxz1, bhz1, pP0, M, HDIM, HDIM, 0);
    sgemm_kernel<<<gH, 256>>>(pY, wxr1, bhr1, pP1, M, HDIM, HDIM, 0);
    sgemm_kernel<<<gH, 256>>>(pY, wxg1, bhg1, pP2, M, HDIM, HDIM, 0);

    // layer 1 scan -> g_Y (overwrites Y0, no longer needed)
    scan_kernel<<<NCTA, 256, SMEM_BYTES>>>(whz1, whr1, whg1, hidden, 1, hfin);

    // output projection: (B,S,O)
    sgemm_kernel<<<gO, 256>>>(pY, why_w, why_b, out, M, ODIM, HDIM, 2);
}